// round 10
// baseline (speedup 1.0000x reference)
#include <cuda_runtime.h>

#define N_NODES 500000
#define N_EDGES 16000000
#define OUT_DIM 112
#define DEG_PAD 128          // Poisson(32): P(deg>64)~2e-6/node -> tail loop needed; P(>128)~0

// ---- device scratch (static globals; referenced ONLY in device code) ----
__device__ int    g_cnt[N_NODES];
__device__ int    g_bucket[(long long)N_NODES * DEG_PAD];  // 256MB: src ids grouped by dst
__device__ float  g_dinv[N_NODES];
__device__ float4 g_ta[N_NODES];          // ping
__device__ float4 g_tb[N_NODES];          // pong

// ---------------------------------------------------------------------------
// Bucket fill: 8 edges/thread; atomics front-batched, stores drain after.
__global__ void __launch_bounds__(256)
k_fillb(const int4* __restrict__ s4, const int4* __restrict__ d4) {
    int i = blockIdx.x * blockDim.x + threadIdx.x;
    if (i >= N_EDGES / 8) return;
    int4 sA = s4[2 * i],     dA = d4[2 * i];
    int4 sB = s4[2 * i + 1], dB = d4[2 * i + 1];

    int p0 = atomicAdd(&g_cnt[dA.x], 1);
    int p1 = atomicAdd(&g_cnt[dA.y], 1);
    int p2 = atomicAdd(&g_cnt[dA.z], 1);
    int p3 = atomicAdd(&g_cnt[dA.w], 1);
    int p4 = atomicAdd(&g_cnt[dB.x], 1);
    int p5 = atomicAdd(&g_cnt[dB.y], 1);
    int p6 = atomicAdd(&g_cnt[dB.z], 1);
    int p7 = atomicAdd(&g_cnt[dB.w], 1);

    if (p0 < DEG_PAD) g_bucket[(long long)dA.x * DEG_PAD + p0] = sA.x;
    if (p1 < DEG_PAD) g_bucket[(long long)dA.y * DEG_PAD + p1] = sA.y;
    if (p2 < DEG_PAD) g_bucket[(long long)dA.z * DEG_PAD + p2] = sA.z;
    if (p3 < DEG_PAD) g_bucket[(long long)dA.w * DEG_PAD + p3] = sA.w;
    if (p4 < DEG_PAD) g_bucket[(long long)dB.x * DEG_PAD + p4] = sB.x;
    if (p5 < DEG_PAD) g_bucket[(long long)dB.y * DEG_PAD + p5] = sB.y;
    if (p6 < DEG_PAD) g_bucket[(long long)dB.z * DEG_PAD + p6] = sB.z;
    if (p7 < DEG_PAD) g_bucket[(long long)dB.w * DEG_PAD + p7] = sB.w;
}

// Layer-1 node transform: dinv = rsqrt(deg+1); t~ = dinv * (x @ W1^T)
__global__ void k_l1(const float* __restrict__ x, const float* __restrict__ W1) {
    __shared__ float sW[32];                    // W1 is [4,8]
    if (threadIdx.x < 32) sW[threadIdx.x] = W1[threadIdx.x];
    __syncthreads();
    int i = blockIdx.x * blockDim.x + threadIdx.x;
    if (i >= N_NODES) return;
    float dinv = rsqrtf((float)g_cnt[i] + 1.0f);
    g_dinv[i] = dinv;
    const float4* x4 = (const float4*)x;
    float4 xa = x4[2 * i], xb = x4[2 * i + 1];
    float t[4];
#pragma unroll
    for (int o = 0; o < 4; o++) {
        const float* w = sW + 8 * o;
        t[o] = w[0]*xa.x + w[1]*xa.y + w[2]*xa.z + w[3]*xa.w
             + w[4]*xb.x + w[5]*xb.y + w[6]*xb.z + w[7]*xb.w;
    }
    g_ta[i] = make_float4(dinv*t[0], dinv*t[1], dinv*t[2], dinv*t[3]);
}

// Persistent fused conv. 4 nodes/warp-iteration (2 per half-warp), grid-stride
// over node quads with cross-iteration software pipelining:
//   - next quad's cnt load issued BEFORE current gathers
//   - next quad's adj loads issued AFTER gathers (cnt landed), BEFORE reduce
// so the cnt->adj->gather dependency chain is paid once, not per iteration.
template<int IN, int OUT, bool RELU, bool SRC_A, bool FINAL>
__global__ void __launch_bounds__(256)
k_conv(const float* __restrict__ W, const float* __restrict__ b,
       float* __restrict__ hout) {
    const float* tin = SRC_A ? (const float*)g_ta : (const float*)g_tb;
    float* tout = FINAL ? hout : (SRC_A ? (float*)g_tb : (float*)g_ta);

    const int NQ = N_NODES / 4;                     // 125000 quads
    int lane = threadIdx.x & 31;
    int half = lane >> 4;
    int l16  = lane & 15;
    int gwarp = (blockIdx.x * blockDim.x + threadIdx.x) >> 5;
    int warpsTotal = (gridDim.x * blockDim.x) >> 5;

    int e0 = 2 * l16, e1 = 2 * l16 + 32;

    int q = gwarp;
    if (q >= NQ) return;

    // prologue: load state for first quad
    int nbase = q * 4 + half * 2;
    int2 dg = __ldg((const int2*)(g_cnt + nbase));
    int deg0 = min(dg.x, DEG_PAD), deg1 = min(dg.y, DEG_PAD);
    const int* a0 = g_bucket + (long long)nbase * DEG_PAD;
    const int* a1 = a0 + DEG_PAD;
    int2 s00 = (e0 < deg0) ? __ldg((const int2*)(a0 + e0)) : make_int2(0, 0);
    int2 s01 = (e1 < deg0) ? __ldg((const int2*)(a0 + e1)) : make_int2(0, 0);
    int2 s10 = (e0 < deg1) ? __ldg((const int2*)(a1 + e0)) : make_int2(0, 0);
    int2 s11 = (e1 < deg1) ? __ldg((const int2*)(a1 + e1)) : make_int2(0, 0);

    while (true) {
        int qn = q + warpsTotal;
        bool hasNext = (qn < NQ);
        int nbaseN = qn * 4 + half * 2;
        // stage A: next quad's degree load (in flight during gathers)
        int2 dgN = hasNext ? __ldg((const int2*)(g_cnt + nbaseN)) : make_int2(0, 0);

        // current gathers (front-batched, predicated)
        float acc0[IN], acc1[IN];
#pragma unroll
        for (int c = 0; c < IN; c++) { acc0[c] = 0.f; acc1[c] = 0.f; }

#define GATHER(ACC, SIDX, OK)                                           \
        if (OK) {                                                       \
            if (IN == 4) {                                              \
                float4 v = __ldg((const float4*)tin + (SIDX));          \
                ACC[0] += v.x; ACC[1] += v.y; ACC[2] += v.z; ACC[3] += v.w; \
            } else {                                                    \
                float2 v = __ldg((const float2*)tin + (SIDX));          \
                ACC[0] += v.x; ACC[1] += v.y;                           \
            }                                                           \
        }
        GATHER(acc0, s00.x, e0     < deg0)
        GATHER(acc0, s00.y, e0 + 1 < deg0)
        GATHER(acc0, s01.x, e1     < deg0)
        GATHER(acc0, s01.y, e1 + 1 < deg0)
        GATHER(acc1, s10.x, e0     < deg1)
        GATHER(acc1, s10.y, e0 + 1 < deg1)
        GATHER(acc1, s11.x, e1     < deg1)
        GATHER(acc1, s11.y, e1 + 1 < deg1)

        // rare tails: deg > 64
        for (int e = 64 + l16; e < deg0; e += 16) {
            int s = __ldg(a0 + e);
            GATHER(acc0, s, true)
        }
        for (int e = 64 + l16; e < deg1; e += 16) {
            int s = __ldg(a1 + e);
            GATHER(acc1, s, true)
        }
#undef GATHER

        // stage B: next quad's adjacency loads (dgN has landed under gathers)
        int deg0N = min(dgN.x, DEG_PAD), deg1N = min(dgN.y, DEG_PAD);
        const int* a0N = g_bucket + (long long)nbaseN * DEG_PAD;
        const int* a1N = a0N + DEG_PAD;
        int2 s00N = (hasNext && e0 < deg0N) ? __ldg((const int2*)(a0N + e0)) : make_int2(0, 0);
        int2 s01N = (hasNext && e1 < deg0N) ? __ldg((const int2*)(a0N + e1)) : make_int2(0, 0);
        int2 s10N = (hasNext && e0 < deg1N) ? __ldg((const int2*)(a1N + e0)) : make_int2(0, 0);
        int2 s11N = (hasNext && e1 < deg1N) ? __ldg((const int2*)(a1N + e1)) : make_int2(0, 0);

        // butterfly within each half-warp (masks 1,2,4,8 preserve bit 4)
#pragma unroll
        for (int o = 8; o; o >>= 1) {
#pragma unroll
            for (int c = 0; c < IN; c++) {
                acc0[c] += __shfl_xor_sync(0xffffffffu, acc0[c], o);
                acc1[c] += __shfl_xor_sync(0xffffffffu, acc1[c], o);
            }
        }

        // epilogue: lane 0 -> nbase, lane 1 -> nbase+1
        if (l16 < 2) {
            int node = nbase + l16;
            float dinv = __ldg(g_dinv + node);
            float accv[IN];
#pragma unroll
            for (int c = 0; c < IN; c++) accv[c] = (l16 == 0) ? acc0[c] : acc1[c];

            float h[IN];
            if (IN == 4) {
                float4 sv = __ldg((const float4*)tin + node);
                float self[4] = {sv.x, sv.y, sv.z, sv.w};
#pragma unroll
                for (int c = 0; c < 4; c++) {
                    float z = dinv * (accv[c] + self[c]) + __ldg(b + c);
                    h[c] = RELU ? fmaxf(z, 0.f) : tanhf(z);
                }
            } else {
                float2 sv = __ldg((const float2*)tin + node);
                float self[2] = {sv.x, sv.y};
#pragma unroll
                for (int c = 0; c < 2; c++) {
                    float z = dinv * (accv[c] + self[c]) + __ldg(b + c);
                    h[c] = RELU ? fmaxf(z, 0.f) : tanhf(z);
                }
            }
            if (FINAL) {
                ((float2*)tout)[node] = make_float2(h[0], h[1]);
            } else {
                float t[OUT];
#pragma unroll
                for (int o = 0; o < OUT; o++) {
                    float sum = 0.f;
#pragma unroll
                    for (int c = 0; c < IN; c++) sum += __ldg(W + o * IN + c) * h[c];
                    t[o] = dinv * sum;
                }
                if (OUT == 4)
                    ((float4*)tout)[node] = make_float4(t[0], t[1], t[2], t[3]);
                else
                    ((float2*)tout)[node] = make_float2(t[0], t[1]);
            }
        }

        if (!hasNext) break;
        q = qn; nbase = nbaseN;
        deg0 = deg0N; deg1 = deg1N; a0 = a0N; a1 = a1N;
        s00 = s00N; s01 = s01N; s10 = s10N; s11 = s11N;
    }
}

// Classifier (separate streaming kernel — coalesced 224MB store):
__global__ void __launch_bounds__(256)
k_cls(const float* __restrict__ Wc, const float* __restrict__ bc,
      float4* __restrict__ out, const float* __restrict__ h4) {
    __shared__ float sW[2 * OUT_DIM], sb[OUT_DIM];
    for (int j = threadIdx.x; j < 2 * OUT_DIM; j += blockDim.x) sW[j] = Wc[j];
    for (int j = threadIdx.x; j < OUT_DIM; j += blockDim.x)     sb[j] = bc[j];
    __syncthreads();
    const long long TOTAL = (long long)N_NODES * (OUT_DIM / 4);
    long long idx = (long long)blockIdx.x * blockDim.x + threadIdx.x;
    if (idx >= TOTAL) return;
    int n  = (int)(idx / (OUT_DIM / 4));
    int kq = (int)(idx - (long long)n * (OUT_DIM / 4));
    float2 h = __ldg((const float2*)h4 + n);
    int k = kq * 4;
    float4 r;
    r.x = sW[2*(k+0)] * h.x + sW[2*(k+0)+1] * h.y + sb[k+0];
    r.y = sW[2*(k+1)] * h.x + sW[2*(k+1)+1] * h.y + sb[k+1];
    r.z = sW[2*(k+2)] * h.x + sW[2*(k+2)+1] * h.y + sb[k+2];
    r.w = sW[2*(k+3)] * h.x + sW[2*(k+3)+1] * h.y + sb[k+3];
    out[idx] = r;
}

// ---------------------------------------------------------------------------
extern "C" void kernel_launch(void* const* d_in, const int* in_sizes, int n_in,
                              void* d_out, int out_size) {
    const float* x   = (const float*)d_in[0];
    const int*   ei  = (const int*)d_in[1];       // [2, E]
    const float* W1  = (const float*)d_in[2];
    const float* b1  = (const float*)d_in[3];
    const float* W2  = (const float*)d_in[4];
    const float* b2  = (const float*)d_in[5];
    const float* W3  = (const float*)d_in[6];
    const float* b3  = (const float*)d_in[7];
    const float* W4  = (const float*)d_in[8];
    const float* b4  = (const float*)d_in[9];
    const float* Wc  = (const float*)d_in[10];
    const float* bc  = (const float*)d_in[11];

    const int4* src4 = (const int4*)ei;
    const int4* dst4 = (const int4*)(ei + N_EDGES);

    float* out  = (float*)d_out;                         // [N, 112]
    float* hout = out + (long long)N_NODES * OUT_DIM;    // [N, 2] tail

    const int TB = 256;
    const int nodeBlocks = (N_NODES + TB - 1) / TB;
    const int fillBlocks = (N_EDGES / 8 + TB - 1) / TB;
    const int convBlocks = 1184;                // 148 SM x 8 blocks, persistent-ish

    // Adjacency build (memset degree, then single fused pass)
    void* cntPtr = nullptr;
    cudaGetSymbolAddress(&cntPtr, g_cnt);
    cudaMemsetAsync(cntPtr, 0, N_NODES * sizeof(int));
    k_fillb<<<fillBlocks, TB>>>(src4, dst4);

    // Layer pipeline (gather-fused, persistent warps)
    k_l1<<<nodeBlocks, TB>>>(x, W1);
    k_conv<4, 4, true,  true,  false><<<convBlocks, TB>>>(W2, b1, nullptr);
    k_conv<4, 2, false, false, false><<<convBlocks, TB>>>(W3, b2, nullptr);
    k_conv<2, 2, true,  true,  false><<<convBlocks, TB>>>(W4, b3, nullptr);
    k_conv<2, 2, false, false, true ><<<convBlocks, TB>>>(nullptr, b4, hout);

    const long long clsTotal = (long long)N_NODES * (OUT_DIM / 4);
    int clsBlocks = (int)((clsTotal + TB - 1) / TB);
    k_cls<<<clsBlocks, TB>>>(Wc, bc, (float4*)out, hout);
}

// round 11
// speedup vs baseline: 1.0612x; 1.0612x over previous
#include <cuda_runtime.h>

#define N_NODES 500000
#define N_EDGES 16000000
#define OUT_DIM 112
#define DEG_PAD 128          // Poisson(32): P(deg>64)~2e-6/node -> tail loop kept; P(>128)~0

// ---- device scratch (static globals; referenced ONLY in device code) ----
__device__ int    g_cnt[N_NODES];
__device__ int    g_bucket[(long long)N_NODES * DEG_PAD];  // 256MB: src ids grouped by dst
__device__ float  g_dinv[N_NODES];
__device__ float4 g_ta[N_NODES];          // ping
__device__ float4 g_tb[N_NODES];          // pong

// ---------------------------------------------------------------------------
// Bucket fill: 8 edges/thread; atomics front-batched, stores drain after.
__global__ void __launch_bounds__(256)
k_fillb(const int4* __restrict__ s4, const int4* __restrict__ d4) {
    int i = blockIdx.x * blockDim.x + threadIdx.x;
    if (i >= N_EDGES / 8) return;
    int4 sA = s4[2 * i],     dA = d4[2 * i];
    int4 sB = s4[2 * i + 1], dB = d4[2 * i + 1];

    int p0 = atomicAdd(&g_cnt[dA.x], 1);
    int p1 = atomicAdd(&g_cnt[dA.y], 1);
    int p2 = atomicAdd(&g_cnt[dA.z], 1);
    int p3 = atomicAdd(&g_cnt[dA.w], 1);
    int p4 = atomicAdd(&g_cnt[dB.x], 1);
    int p5 = atomicAdd(&g_cnt[dB.y], 1);
    int p6 = atomicAdd(&g_cnt[dB.z], 1);
    int p7 = atomicAdd(&g_cnt[dB.w], 1);

    if (p0 < DEG_PAD) g_bucket[(long long)dA.x * DEG_PAD + p0] = sA.x;
    if (p1 < DEG_PAD) g_bucket[(long long)dA.y * DEG_PAD + p1] = sA.y;
    if (p2 < DEG_PAD) g_bucket[(long long)dA.z * DEG_PAD + p2] = sA.z;
    if (p3 < DEG_PAD) g_bucket[(long long)dA.w * DEG_PAD + p3] = sA.w;
    if (p4 < DEG_PAD) g_bucket[(long long)dB.x * DEG_PAD + p4] = sB.x;
    if (p5 < DEG_PAD) g_bucket[(long long)dB.y * DEG_PAD + p5] = sB.y;
    if (p6 < DEG_PAD) g_bucket[(long long)dB.z * DEG_PAD + p6] = sB.z;
    if (p7 < DEG_PAD) g_bucket[(long long)dB.w * DEG_PAD + p7] = sB.w;
}

// Layer-1 node transform: dinv = rsqrt(deg+1); t~ = dinv * (x @ W1^T)
__global__ void k_l1(const float* __restrict__ x, const float* __restrict__ W1) {
    __shared__ float sW[32];                    // W1 is [4,8]
    if (threadIdx.x < 32) sW[threadIdx.x] = W1[threadIdx.x];
    __syncthreads();
    int i = blockIdx.x * blockDim.x + threadIdx.x;
    if (i >= N_NODES) return;
    float dinv = rsqrtf((float)g_cnt[i] + 1.0f);
    g_dinv[i] = dinv;
    const float4* x4 = (const float4*)x;
    float4 xa = x4[2 * i], xb = x4[2 * i + 1];
    float t[4];
#pragma unroll
    for (int o = 0; o < 4; o++) {
        const float* w = sW + 8 * o;
        t[o] = w[0]*xa.x + w[1]*xa.y + w[2]*xa.z + w[3]*xa.w
             + w[4]*xb.x + w[5]*xb.y + w[6]*xb.z + w[7]*xb.w;
    }
    g_ta[i] = make_float4(dinv*t[0], dinv*t[1], dinv*t[2], dinv*t[3]);
}

// Fused gather + epilogue + next transform. 8 nodes/warp: each half-warp (16
// lanes) processes 4 consecutive nodes, straight-line: 1 int4 degree load,
// 8 int2 adj loads, 16 predicated gathers all front-batched (deg<=64 fast
// path; tail loops for rare deg>64). Butterfly broadcasts all 4 sums to every
// lane; lanes 0-3 of each half do the 4 epilogues in parallel.
template<int IN, int OUT, bool RELU, bool SRC_A, bool FINAL>
__global__ void __launch_bounds__(256)
k_conv(const float* __restrict__ W, const float* __restrict__ b,
       float* __restrict__ hout) {
    const float* tin = SRC_A ? (const float*)g_ta : (const float*)g_tb;
    float* tout = FINAL ? hout : (SRC_A ? (float*)g_tb : (float*)g_ta);

    int gw   = (blockIdx.x * blockDim.x + threadIdx.x) >> 5;  // warp id
    if (gw >= N_NODES / 8) return;            // 62500 warps, N%8==0
    int lane = threadIdx.x & 31;
    int half = lane >> 4;
    int l16  = lane & 15;
    int base = gw * 8 + half * 4;             // this half's four nodes

    // one int4 degree load (base % 4 == 0 -> 16B aligned)
    int4 dg = __ldg((const int4*)(g_cnt + base));
    int deg0 = min(dg.x, DEG_PAD), deg1 = min(dg.y, DEG_PAD);
    int deg2 = min(dg.z, DEG_PAD), deg3 = min(dg.w, DEG_PAD);
    const int* a0 = g_bucket + (long long)base * DEG_PAD;
    const int* a1 = a0 + DEG_PAD;
    const int* a2 = a1 + DEG_PAD;
    const int* a3 = a2 + DEG_PAD;

    int e0 = 2 * l16, e1 = 2 * l16 + 32;

    // phase 1: batch adjacency loads (int2, predicated; cover deg<=64)
    int2 s00 = (e0 < deg0) ? __ldg((const int2*)(a0 + e0)) : make_int2(0, 0);
    int2 s01 = (e1 < deg0) ? __ldg((const int2*)(a0 + e1)) : make_int2(0, 0);
    int2 s10 = (e0 < deg1) ? __ldg((const int2*)(a1 + e0)) : make_int2(0, 0);
    int2 s11 = (e1 < deg1) ? __ldg((const int2*)(a1 + e1)) : make_int2(0, 0);
    int2 s20 = (e0 < deg2) ? __ldg((const int2*)(a2 + e0)) : make_int2(0, 0);
    int2 s21 = (e1 < deg2) ? __ldg((const int2*)(a2 + e1)) : make_int2(0, 0);
    int2 s30 = (e0 < deg3) ? __ldg((const int2*)(a3 + e0)) : make_int2(0, 0);
    int2 s31 = (e1 < deg3) ? __ldg((const int2*)(a3 + e1)) : make_int2(0, 0);

    // phase 2: batch feature gathers (up to 16, predicated individually)
    float acc0[IN], acc1[IN], acc2[IN], acc3[IN];
#pragma unroll
    for (int c = 0; c < IN; c++) { acc0[c] = 0.f; acc1[c] = 0.f; acc2[c] = 0.f; acc3[c] = 0.f; }

#define GATHER(ACC, SIDX, OK)                                         \
    if (OK) {                                                         \
        if (IN == 4) {                                                \
            float4 v = __ldg((const float4*)tin + (SIDX));            \
            ACC[0] += v.x; ACC[1] += v.y; ACC[2] += v.z; ACC[3] += v.w; \
        } else {                                                      \
            float2 v = __ldg((const float2*)tin + (SIDX));            \
            ACC[0] += v.x; ACC[1] += v.y;                             \
        }                                                             \
    }
    GATHER(acc0, s00.x, e0     < deg0)
    GATHER(acc0, s00.y, e0 + 1 < deg0)
    GATHER(acc0, s01.x, e1     < deg0)
    GATHER(acc0, s01.y, e1 + 1 < deg0)
    GATHER(acc1, s10.x, e0     < deg1)
    GATHER(acc1, s10.y, e0 + 1 < deg1)
    GATHER(acc1, s11.x, e1     < deg1)
    GATHER(acc1, s11.y, e1 + 1 < deg1)
    GATHER(acc2, s20.x, e0     < deg2)
    GATHER(acc2, s20.y, e0 + 1 < deg2)
    GATHER(acc2, s21.x, e1     < deg2)
    GATHER(acc2, s21.y, e1 + 1 < deg2)
    GATHER(acc3, s30.x, e0     < deg3)
    GATHER(acc3, s30.y, e0 + 1 < deg3)
    GATHER(acc3, s31.x, e1     < deg3)
    GATHER(acc3, s31.y, e1 + 1 < deg3)

    // rare tails: deg > 64
    for (int e = 64 + l16; e < deg0; e += 16) { int s = __ldg(a0 + e); GATHER(acc0, s, true) }
    for (int e = 64 + l16; e < deg1; e += 16) { int s = __ldg(a1 + e); GATHER(acc1, s, true) }
    for (int e = 64 + l16; e < deg2; e += 16) { int s = __ldg(a2 + e); GATHER(acc2, s, true) }
    for (int e = 64 + l16; e < deg3; e += 16) { int s = __ldg(a3 + e); GATHER(acc3, s, true) }
#undef GATHER

    // butterfly within each half-warp (masks 1,2,4,8 preserve bit 4)
#pragma unroll
    for (int o = 8; o; o >>= 1) {
#pragma unroll
        for (int c = 0; c < IN; c++) {
            acc0[c] += __shfl_xor_sync(0xffffffffu, acc0[c], o);
            acc1[c] += __shfl_xor_sync(0xffffffffu, acc1[c], o);
            acc2[c] += __shfl_xor_sync(0xffffffffu, acc2[c], o);
            acc3[c] += __shfl_xor_sync(0xffffffffu, acc3[c], o);
        }
    }

    // epilogue: lanes 0-3 -> nodes base..base+3 (sums replicated to all lanes)
    if (l16 < 4) {
        int node = base + l16;
        float dinv = __ldg(g_dinv + node);
        float accv[IN];
#pragma unroll
        for (int c = 0; c < IN; c++)
            accv[c] = (l16 == 0) ? acc0[c] : (l16 == 1) ? acc1[c]
                    : (l16 == 2) ? acc2[c] : acc3[c];

        float h[IN];
        if (IN == 4) {
            float4 sv = __ldg((const float4*)tin + node);
            float self[4] = {sv.x, sv.y, sv.z, sv.w};
#pragma unroll
            for (int c = 0; c < 4; c++) {
                float z = dinv * (accv[c] + self[c]) + __ldg(b + c);
                h[c] = RELU ? fmaxf(z, 0.f) : tanhf(z);
            }
        } else {
            float2 sv = __ldg((const float2*)tin + node);
            float self[2] = {sv.x, sv.y};
#pragma unroll
            for (int c = 0; c < 2; c++) {
                float z = dinv * (accv[c] + self[c]) + __ldg(b + c);
                h[c] = RELU ? fmaxf(z, 0.f) : tanhf(z);
            }
        }
        if (FINAL) {
            ((float2*)tout)[node] = make_float2(h[0], h[1]);
        } else {
            float t[OUT];
#pragma unroll
            for (int o = 0; o < OUT; o++) {
                float sum = 0.f;
#pragma unroll
                for (int c = 0; c < IN; c++) sum += __ldg(W + o * IN + c) * h[c];
                t[o] = dinv * sum;
            }
            if (OUT == 4)
                ((float4*)tout)[node] = make_float4(t[0], t[1], t[2], t[3]);
            else
                ((float2*)tout)[node] = make_float2(t[0], t[1]);
        }
    }
}

// Classifier (separate streaming kernel — coalesced 224MB store):
__global__ void __launch_bounds__(256)
k_cls(const float* __restrict__ Wc, const float* __restrict__ bc,
      float4* __restrict__ out, const float* __restrict__ h4) {
    __shared__ float sW[2 * OUT_DIM], sb[OUT_DIM];
    for (int j = threadIdx.x; j < 2 * OUT_DIM; j += blockDim.x) sW[j] = Wc[j];
    for (int j = threadIdx.x; j < OUT_DIM; j += blockDim.x)     sb[j] = bc[j];
    __syncthreads();
    const long long TOTAL = (long long)N_NODES * (OUT_DIM / 4);
    long long idx = (long long)blockIdx.x * blockDim.x + threadIdx.x;
    if (idx >= TOTAL) return;
    int n  = (int)(idx / (OUT_DIM / 4));
    int kq = (int)(idx - (long long)n * (OUT_DIM / 4));
    float2 h = __ldg((const float2*)h4 + n);
    int k = kq * 4;
    float4 r;
    r.x = sW[2*(k+0)] * h.x + sW[2*(k+0)+1] * h.y + sb[k+0];
    r.y = sW[2*(k+1)] * h.x + sW[2*(k+1)+1] * h.y + sb[k+1];
    r.z = sW[2*(k+2)] * h.x + sW[2*(k+2)+1] * h.y + sb[k+2];
    r.w = sW[2*(k+3)] * h.x + sW[2*(k+3)+1] * h.y + sb[k+3];
    out[idx] = r;
}

// ---------------------------------------------------------------------------
extern "C" void kernel_launch(void* const* d_in, const int* in_sizes, int n_in,
                              void* d_out, int out_size) {
    const float* x   = (const float*)d_in[0];
    const int*   ei  = (const int*)d_in[1];       // [2, E]
    const float* W1  = (const float*)d_in[2];
    const float* b1  = (const float*)d_in[3];
    const float* W2  = (const float*)d_in[4];
    const float* b2  = (const float*)d_in[5];
    const float* W3  = (const float*)d_in[6];
    const float* b3  = (const float*)d_in[7];
    const float* W4  = (const float*)d_in[8];
    const float* b4  = (const float*)d_in[9];
    const float* Wc  = (const float*)d_in[10];
    const float* bc  = (const float*)d_in[11];

    const int4* src4 = (const int4*)ei;
    const int4* dst4 = (const int4*)(ei + N_EDGES);

    float* out  = (float*)d_out;                         // [N, 112]
    float* hout = out + (long long)N_NODES * OUT_DIM;    // [N, 2] tail

    const int TB = 256;
    const int nodeBlocks = (N_NODES + TB - 1) / TB;
    const int fillBlocks = (N_EDGES / 8 + TB - 1) / TB;
    // 8 nodes per warp -> N/8 warps -> N*4 threads
    const int convBlocks = (N_NODES / 8 * 32 + TB - 1) / TB;

    // Adjacency build (memset degree, then single fused pass)
    void* cntPtr = nullptr;
    cudaGetSymbolAddress(&cntPtr, g_cnt);
    cudaMemsetAsync(cntPtr, 0, N_NODES * sizeof(int));
    k_fillb<<<fillBlocks, TB>>>(src4, dst4);

    // Layer pipeline (gather-fused)
    k_l1<<<nodeBlocks, TB>>>(x, W1);
    k_conv<4, 4, true,  true,  false><<<convBlocks, TB>>>(W2, b1, nullptr); // relu(b1)->W2, ta->tb
    k_conv<4, 2, false, false, false><<<convBlocks, TB>>>(W3, b2, nullptr); // tanh(b2)->W3, tb->ta
    k_conv<2, 2, true,  true,  false><<<convBlocks, TB>>>(W4, b3, nullptr); // relu(b3)->W4, ta->tb
    k_conv<2, 2, false, false, true ><<<convBlocks, TB>>>(nullptr, b4, hout); // tanh(b4) -> hout

    const long long clsTotal = (long long)N_NODES * (OUT_DIM / 4);
    int clsBlocks = (int)((clsTotal + TB - 1) / TB);
    k_cls<<<clsBlocks, TB>>>(Wc, bc, (float4*)out, hout);
}

// round 12
// speedup vs baseline: 1.1052x; 1.0415x over previous
#include <cuda_runtime.h>

#define N_NODES 500000
#define N_EDGES 16000000
#define OUT_DIM 112
#define DEG_PAD 128          // Poisson(32): max deg ~61; fast path 64, tail loop for safety

// ---- device scratch (static globals; referenced ONLY in device code) ----
__device__ int    g_cnt[N_NODES];
__device__ int    g_bucket[(long long)N_NODES * DEG_PAD];  // 256MB: src ids grouped by dst
__device__ float  g_dinv[N_NODES];
__device__ float4 g_ta[N_NODES];          // ping
__device__ float4 g_tb[N_NODES];          // pong

// ---------------------------------------------------------------------------
// Bucket fill: 8 edges/thread; atomics front-batched, stores drain after.
__global__ void __launch_bounds__(256)
k_fillb(const int4* __restrict__ s4, const int4* __restrict__ d4) {
    int i = blockIdx.x * blockDim.x + threadIdx.x;
    if (i >= N_EDGES / 8) return;
    int4 sA = s4[2 * i],     dA = d4[2 * i];
    int4 sB = s4[2 * i + 1], dB = d4[2 * i + 1];

    int p0 = atomicAdd(&g_cnt[dA.x], 1);
    int p1 = atomicAdd(&g_cnt[dA.y], 1);
    int p2 = atomicAdd(&g_cnt[dA.z], 1);
    int p3 = atomicAdd(&g_cnt[dA.w], 1);
    int p4 = atomicAdd(&g_cnt[dB.x], 1);
    int p5 = atomicAdd(&g_cnt[dB.y], 1);
    int p6 = atomicAdd(&g_cnt[dB.z], 1);
    int p7 = atomicAdd(&g_cnt[dB.w], 1);

    if (p0 < DEG_PAD) g_bucket[(long long)dA.x * DEG_PAD + p0] = sA.x;
    if (p1 < DEG_PAD) g_bucket[(long long)dA.y * DEG_PAD + p1] = sA.y;
    if (p2 < DEG_PAD) g_bucket[(long long)dA.z * DEG_PAD + p2] = sA.z;
    if (p3 < DEG_PAD) g_bucket[(long long)dA.w * DEG_PAD + p3] = sA.w;
    if (p4 < DEG_PAD) g_bucket[(long long)dB.x * DEG_PAD + p4] = sB.x;
    if (p5 < DEG_PAD) g_bucket[(long long)dB.y * DEG_PAD + p5] = sB.y;
    if (p6 < DEG_PAD) g_bucket[(long long)dB.z * DEG_PAD + p6] = sB.z;
    if (p7 < DEG_PAD) g_bucket[(long long)dB.w * DEG_PAD + p7] = sB.w;
}

// Layer-1 node transform: dinv = rsqrt(deg+1); t~ = dinv * (x @ W1^T)
__global__ void k_l1(const float* __restrict__ x, const float* __restrict__ W1) {
    __shared__ float sW[32];                    // W1 is [4,8]
    if (threadIdx.x < 32) sW[threadIdx.x] = W1[threadIdx.x];
    __syncthreads();
    int i = blockIdx.x * blockDim.x + threadIdx.x;
    if (i >= N_NODES) return;
    float dinv = rsqrtf((float)g_cnt[i] + 1.0f);
    g_dinv[i] = dinv;
    const float4* x4 = (const float4*)x;
    float4 xa = x4[2 * i], xb = x4[2 * i + 1];
    float t[4];
#pragma unroll
    for (int o = 0; o < 4; o++) {
        const float* w = sW + 8 * o;
        t[o] = w[0]*xa.x + w[1]*xa.y + w[2]*xa.z + w[3]*xa.w
             + w[4]*xb.x + w[5]*xb.y + w[6]*xb.z + w[7]*xb.w;
    }
    g_ta[i] = make_float4(dinv*t[0], dinv*t[1], dinv*t[2], dinv*t[3]);
}

// Fused gather + epilogue + next transform. 4 nodes/warp (R8 geometry): each
// half-warp (16 lanes) handles 2 nodes; per node ONE int4 adjacency load
// (4*l16, covers deg<=64 across 16 lanes) then predicated gathers, all
// front-batched. Tail loops handle the (absent at this size) deg>64 case.
// Lanes 0/1 of each half do the two epilogues in parallel.
template<int IN, int OUT, bool RELU, bool SRC_A, bool FINAL>
__global__ void __launch_bounds__(256)
k_conv(const float* __restrict__ W, const float* __restrict__ b,
       float* __restrict__ hout) {
    const float* tin = SRC_A ? (const float*)g_ta : (const float*)g_tb;
    float* tout = FINAL ? hout : (SRC_A ? (float*)g_tb : (float*)g_ta);

    int gw   = (blockIdx.x * blockDim.x + threadIdx.x) >> 5;  // warp id
    int lane = threadIdx.x & 31;
    int half = lane >> 4;
    int l16  = lane & 15;
    int nbase = gw * 4 + half * 2;          // this half's two nodes
    if (nbase >= N_NODES) return;           // N % 4 == 0 -> both nodes valid

    int2 dg = __ldg((const int2*)(g_cnt + nbase));
    int deg0 = min(dg.x, DEG_PAD), deg1 = min(dg.y, DEG_PAD);
    const int* a0 = g_bucket + (long long)nbase * DEG_PAD;
    const int* a1 = a0 + DEG_PAD;

    // phase 1: one int4 adjacency load per node (16B aligned; covers deg<=64)
    int e = 4 * l16;
    int4 s0 = (e < deg0) ? __ldg((const int4*)(a0 + e)) : make_int4(0, 0, 0, 0);
    int4 s1 = (e < deg1) ? __ldg((const int4*)(a1 + e)) : make_int4(0, 0, 0, 0);

    // phase 2: batch feature gathers (up to 8, predicated individually)
    float acc0[IN], acc1[IN];
#pragma unroll
    for (int c = 0; c < IN; c++) { acc0[c] = 0.f; acc1[c] = 0.f; }

#define GATHER(ACC, SIDX, OK)                                         \
    if (OK) {                                                         \
        if (IN == 4) {                                                \
            float4 v = __ldg((const float4*)tin + (SIDX));            \
            ACC[0] += v.x; ACC[1] += v.y; ACC[2] += v.z; ACC[3] += v.w; \
        } else {                                                      \
            float2 v = __ldg((const float2*)tin + (SIDX));            \
            ACC[0] += v.x; ACC[1] += v.y;                             \
        }                                                             \
    }
    GATHER(acc0, s0.x, e     < deg0)
    GATHER(acc0, s0.y, e + 1 < deg0)
    GATHER(acc0, s0.z, e + 2 < deg0)
    GATHER(acc0, s0.w, e + 3 < deg0)
    GATHER(acc1, s1.x, e     < deg1)
    GATHER(acc1, s1.y, e + 1 < deg1)
    GATHER(acc1, s1.z, e + 2 < deg1)
    GATHER(acc1, s1.w, e + 3 < deg1)

    // rare tails: deg > 64 (not hit at this problem size; correctness guard)
    for (int t = 64 + l16; t < deg0; t += 16) { int s = __ldg(a0 + t); GATHER(acc0, s, true) }
    for (int t = 64 + l16; t < deg1; t += 16) { int s = __ldg(a1 + t); GATHER(acc1, s, true) }
#undef GATHER

    // butterfly within each half-warp (masks 1,2,4,8 preserve bit 4)
#pragma unroll
    for (int o = 8; o; o >>= 1) {
#pragma unroll
        for (int c = 0; c < IN; c++) {
            acc0[c] += __shfl_xor_sync(0xffffffffu, acc0[c], o);
            acc1[c] += __shfl_xor_sync(0xffffffffu, acc1[c], o);
        }
    }

    // epilogue: lane 0 -> nbase, lane 1 -> nbase+1 (sums replicated to all lanes)
    if (l16 < 2) {
        int node = nbase + l16;
        float dinv = __ldg(g_dinv + node);
        float accv[IN];
#pragma unroll
        for (int c = 0; c < IN; c++) accv[c] = (l16 == 0) ? acc0[c] : acc1[c];

        float h[IN];
        if (IN == 4) {
            float4 sv = __ldg((const float4*)tin + node);
            float self[4] = {sv.x, sv.y, sv.z, sv.w};
#pragma unroll
            for (int c = 0; c < 4; c++) {
                float z = dinv * (accv[c] + self[c]) + __ldg(b + c);
                h[c] = RELU ? fmaxf(z, 0.f) : tanhf(z);
            }
        } else {
            float2 sv = __ldg((const float2*)tin + node);
            float self[2] = {sv.x, sv.y};
#pragma unroll
            for (int c = 0; c < 2; c++) {
                float z = dinv * (accv[c] + self[c]) + __ldg(b + c);
                h[c] = RELU ? fmaxf(z, 0.f) : tanhf(z);
            }
        }
        if (FINAL) {
            ((float2*)tout)[node] = make_float2(h[0], h[1]);
        } else {
            float t[OUT];
#pragma unroll
            for (int o = 0; o < OUT; o++) {
                float sum = 0.f;
#pragma unroll
                for (int c = 0; c < IN; c++) sum += __ldg(W + o * IN + c) * h[c];
                t[o] = dinv * sum;
            }
            if (OUT == 4)
                ((float4*)tout)[node] = make_float4(t[0], t[1], t[2], t[3]);
            else
                ((float2*)tout)[node] = make_float2(t[0], t[1]);
        }
    }
}

// Classifier (separate streaming kernel — coalesced 224MB store):
__global__ void __launch_bounds__(256)
k_cls(const float* __restrict__ Wc, const float* __restrict__ bc,
      float4* __restrict__ out, const float* __restrict__ h4) {
    __shared__ float sW[2 * OUT_DIM], sb[OUT_DIM];
    for (int j = threadIdx.x; j < 2 * OUT_DIM; j += blockDim.x) sW[j] = Wc[j];
    for (int j = threadIdx.x; j < OUT_DIM; j += blockDim.x)     sb[j] = bc[j];
    __syncthreads();
    const long long TOTAL = (long long)N_NODES * (OUT_DIM / 4);
    long long idx = (long long)blockIdx.x * blockDim.x + threadIdx.x;
    if (idx >= TOTAL) return;
    int n  = (int)(idx / (OUT_DIM / 4));
    int kq = (int)(idx - (long long)n * (OUT_DIM / 4));
    float2 h = __ldg((const float2*)h4 + n);
    int k = kq * 4;
    float4 r;
    r.x = sW[2*(k+0)] * h.x + sW[2*(k+0)+1] * h.y + sb[k+0];
    r.y = sW[2*(k+1)] * h.x + sW[2*(k+1)+1] * h.y + sb[k+1];
    r.z = sW[2*(k+2)] * h.x + sW[2*(k+2)+1] * h.y + sb[k+2];
    r.w = sW[2*(k+3)] * h.x + sW[2*(k+3)+1] * h.y + sb[k+3];
    out[idx] = r;
}

// ---------------------------------------------------------------------------
extern "C" void kernel_launch(void* const* d_in, const int* in_sizes, int n_in,
                              void* d_out, int out_size) {
    const float* x   = (const float*)d_in[0];
    const int*   ei  = (const int*)d_in[1];       // [2, E]
    const float* W1  = (const float*)d_in[2];
    const float* b1  = (const float*)d_in[3];
    const float* W2  = (const float*)d_in[4];
    const float* b2  = (const float*)d_in[5];
    const float* W3  = (const float*)d_in[6];
    const float* b3  = (const float*)d_in[7];
    const float* W4  = (const float*)d_in[8];
    const float* b4  = (const float*)d_in[9];
    const float* Wc  = (const float*)d_in[10];
    const float* bc  = (const float*)d_in[11];

    const int4* src4 = (const int4*)ei;
    const int4* dst4 = (const int4*)(ei + N_EDGES);

    float* out  = (float*)d_out;                         // [N, 112]
    float* hout = out + (long long)N_NODES * OUT_DIM;    // [N, 2] tail

    const int TB = 256;
    const int nodeBlocks = (N_NODES + TB - 1) / TB;
    const int fillBlocks = (N_EDGES / 8 + TB - 1) / TB;
    // 4 nodes per warp -> N/4 warps -> N*8 threads
    const int convBlocks = (N_NODES / 4 * 32 + TB - 1) / TB;

    // Adjacency build (memset degree, then single fused pass)
    void* cntPtr = nullptr;
    cudaGetSymbolAddress(&cntPtr, g_cnt);
    cudaMemsetAsync(cntPtr, 0, N_NODES * sizeof(int));
    k_fillb<<<fillBlocks, TB>>>(src4, dst4);

    // Layer pipeline (gather-fused)
    k_l1<<<nodeBlocks, TB>>>(x, W1);
    k_conv<4, 4, true,  true,  false><<<convBlocks, TB>>>(W2, b1, nullptr); // relu(b1)->W2, ta->tb
    k_conv<4, 2, false, false, false><<<convBlocks, TB>>>(W3, b2, nullptr); // tanh(b2)->W3, tb->ta
    k_conv<2, 2, true,  true,  false><<<convBlocks, TB>>>(W4, b3, nullptr); // relu(b3)->W4, ta->tb
    k_conv<2, 2, false, false, true ><<<convBlocks, TB>>>(nullptr, b4, hout); // tanh(b4) -> hout

    const long long clsTotal = (long long)N_NODES * (OUT_DIM / 4);
    int clsBlocks = (int)((clsTotal + TB - 1) / TB);
    k_cls<<<clsBlocks, TB>>>(Wc, bc, (float4*)out, hout);
}